// round 13
// baseline (speedup 1.0000x reference)
#include <cuda_runtime.h>
#include <math.h>

// ---------------- constants ----------------
#define BB 4
#define HFD 128
#define WFD 128
#define KPRE 2000
#define KOUT 500

typedef unsigned long long u64;

// ---------------- scratch (device globals; no allocation allowed) ----------------
__device__ __align__(16) float g_x1[(size_t)4 * 256 * 256 * 64];       // conv1 out
__device__ __align__(16) float g_feat[(size_t)4 * 128 * 128 * 256];    // conv2 out
__device__ __align__(16) float g_segr[(size_t)4 * 128 * 128 * 32];     // reduced seg feats
__device__ __align__(16) float g_scores[4 * 16384];
__device__ __align__(16) float g_reg[4 * 16384 * 2];
__device__ __align__(16) float g_topsc[4 * KPRE];
__device__ __align__(16) float g_locs[4 * KPRE * 2];
__device__ __align__(16) unsigned g_sup[(size_t)4 * KPRE * 64];        // suppression bitmatrix
__device__ int g_sel[4 * KOUT];
__device__ int g_nsel[4];
__device__ int g_tl[4 * KOUT * 2];
__device__ __align__(16) float g_instfull[4 * 128 * 128];
__device__ __align__(16) float g_acc1[(size_t)4 * 128 * 128 * 32];     // instfull pre-bias acc

// transposed/interleaved weights for f32x2 (built per launch by one tiny kernel)
__device__ __align__(16) float g_wt_seg[256 * 256];   // [ci2][c][2]
__device__ __align__(16) float g_wt_r[256 * 32];      // [ci2][co][2]
__device__ __align__(16) float g_wt2[9 * 64 * 256];   // [tap][ci2][co][2]
__device__ __align__(16) float g_wt_h[9 * 128 * 6];   // [tap][ci2][{sc0,sc1,rgy0,rgy1,rgx0,rgx1}]
__device__ __align__(16) float g_wt_pc[9 * 32 * 32];  // [tap][co][ci]  (co-major for instfull/patch)

__device__ __forceinline__ float sigmoidf(float z) { return 1.f / (1.f + expf(-z)); }

// ---- packed f32x2 helpers (u64 as b64 carrier of two floats; "l" constraints) ----
__device__ __forceinline__ void ffma2(u64& acc, u64 a, u64 b) {
    asm("fma.rn.f32x2 %0, %1, %2, %0;" : "+l"(acc) : "l"(a), "l"(b));
}
__device__ __forceinline__ u64 pack2(float v) {
    u64 d; asm("mov.b64 %0, {%1, %1};" : "=l"(d) : "f"(v)); return d;
}
__device__ __forceinline__ float f2sum(u64 a) {
    float lo, hi; asm("mov.b64 {%0, %1}, %2;" : "=f"(lo), "=f"(hi) : "l"(a));
    return lo + hi;
}
__device__ __forceinline__ void f2unpack(u64 a, float& lo, float& hi) {
    asm("mov.b64 {%0, %1}, %2;" : "=f"(lo), "=f"(hi) : "l"(a));
}

// ---------------- merged weight transpose kernel (one launch) ----------------
__global__ void tr_all_kernel(const float* __restrict__ wseg, const float* __restrict__ wr,
                              const float* __restrict__ w2, const float* __restrict__ wsc,
                              const float* __restrict__ wrg, const float* __restrict__ wp1) {
    int idx = blockIdx.x * 256 + threadIdx.x;
    if (idx < 65536) {
        int k = idx & 1, c = (idx >> 1) & 255, ci2 = idx >> 9;
        g_wt_seg[idx] = wseg[(2 * ci2 + k) * 256 + c];
    } else if (idx < 73728) {
        int rel = idx - 65536;
        int k = rel & 1, co = (rel >> 1) & 31, ci2 = rel >> 6;
        g_wt_r[rel] = wr[(2 * ci2 + k) * 32 + co];
    } else if (idx < 221184) {
        int rel = idx - 73728;
        int k = rel & 1, co = (rel >> 1) & 255;
        int r = rel >> 9; int ci2 = r & 31; int tap = r >> 5;
        g_wt2[rel] = w2[(tap * 64 + 2 * ci2 + k) * 256 + co];
    } else if (idx < 228096) {
        int rel = idx - 221184;
        int comp = rel % 6; int entry = rel / 6;
        int ci2 = entry & 127, tap = entry >> 7;
        int e0 = tap * 256 + 2 * ci2;
        float v;
        switch (comp) {
            case 0: v = wsc[e0]; break;
            case 1: v = wsc[e0 + 1]; break;
            case 2: v = wrg[e0 * 2]; break;
            case 3: v = wrg[(e0 + 1) * 2]; break;
            case 4: v = wrg[e0 * 2 + 1]; break;
            default: v = wrg[(e0 + 1) * 2 + 1]; break;
        }
        g_wt_h[rel] = v;
    } else if (idx < 237312) {
        int rel = idx - 228096;                     // [tap][co][ci]
        int tap = rel >> 10, co = (rel >> 5) & 31, ci = rel & 31;
        g_wt_pc[rel] = wp1[(tap * 32 + ci) * 32 + co];
    }
}

// ---------------- conv1: 3x3 s2, 3->64, relu (SAME => iy=2y+ky, pad_lo=0) ----------------
__global__ void conv1_kernel(const float* __restrict__ img, const float* __restrict__ w1,
                             const float* __restrict__ b1) {
    __shared__ __align__(16) float smimg[17 * 17 * 3 + 1];
    __shared__ __align__(16) float wsh[27 * 64];
    __shared__ __align__(16) float sbias[64];
    int x0 = blockIdx.x * 8, y0 = blockIdx.y * 8, b = blockIdx.z;
    int t = threadIdx.x;
    for (int e = t; e < 17 * 17 * 3; e += 256) {
        int r = e / 51, rem = e % 51, c = rem / 3, ci = rem % 3;
        int iy = 2 * y0 + r, ix = 2 * x0 + c;
        smimg[e] = (iy < 512 && ix < 512) ? __ldg(img + ((size_t)(b * 512 + iy) * 512 + ix) * 3 + ci) : 0.f;
    }
    for (int e = t; e < 27 * 64; e += 256) wsh[e] = __ldg(w1 + e);
    if (t < 64) sbias[t] = __ldg(b1 + t);
    __syncthreads();
    int copair = t & 31, py = t >> 5;
    int c0 = copair * 2;
    u64 acc[8];
#pragma unroll
    for (int p = 0; p < 8; p++) acc[p] = 0ull;
#pragma unroll
    for (int ky = 0; ky < 3; ky++) {
        int rowb = (2 * py + ky) * 51;
#pragma unroll
        for (int kx = 0; kx < 3; kx++) {
#pragma unroll
            for (int ci = 0; ci < 3; ci++) {
                u64 w2v = *(const u64*)(wsh + ((ky * 3 + kx) * 3 + ci) * 64 + c0);
                int off = rowb + kx * 3 + ci;
#pragma unroll
                for (int p = 0; p < 8; p++) {
                    u64 vv = pack2(smimg[off + p * 6]);
                    ffma2(acc[p], vv, w2v);
                }
            }
        }
    }
    float2 bb = *(const float2*)(sbias + c0);
    int y = y0 + py;
#pragma unroll
    for (int p = 0; p < 8; p++) {
        float lo, hi; f2unpack(acc[p], lo, hi);
        float2 o;
        o.x = fmaxf(lo + bb.x, 0.f);
        o.y = fmaxf(hi + bb.y, 0.f);
        *(float2*)(g_x1 + ((size_t)(b * 256 + y) * 256 + (x0 + p)) * 64 + c0) = o;
    }
}

// ---------------- conv2: 3x3 s2, 64->256, relu; ci-pair packed ----------------
__global__ void __launch_bounds__(256, 2) conv2_kernel(const float* __restrict__ b2) {
    __shared__ __align__(16) float sm[9 * 17 * 64];
    int x0 = blockIdx.x * 8, y0 = blockIdx.y * 4, b = blockIdx.z;
    int t = threadIdx.x;
    for (int e = t; e < 9 * 17 * 64; e += 256) {
        int ci = e & 63; int rc = e >> 6; int c = rc % 17; int r = rc / 17;
        int iy = 2 * y0 + r, ix = 2 * x0 + c;
        float v = 0.f;
        if (iy < 256 && ix < 256) v = g_x1[((size_t)(b * 256 + iy) * 256 + ix) * 64 + ci];
        sm[e] = v;
    }
    __syncthreads();
    int co4 = t & 63, ry = t >> 6;
    u64 acc[8][4];
#pragma unroll
    for (int p = 0; p < 8; p++)
#pragma unroll
        for (int j = 0; j < 4; j++) acc[p][j] = 0ull;
    const u64* wt2d = (const u64*)g_wt2;
#pragma unroll
    for (int ky = 0; ky < 3; ky++) {
        int r = 2 * ry + ky;
#pragma unroll
        for (int kx = 0; kx < 3; kx++) {
            const float* sbase = sm + (r * 17 + kx) * 64;
            const u64* wb = wt2d + (size_t)((ky * 3 + kx) * 32) * 256 + co4 * 4;
            for (int ci2 = 0; ci2 < 32; ci2++) {
                u64 v[8];
#pragma unroll
                for (int p = 0; p < 8; p++) v[p] = *(const u64*)(sbase + p * 128 + 2 * ci2);
                ulonglong2 wA = *(const ulonglong2*)(wb + (size_t)ci2 * 256);
                ulonglong2 wB = *(const ulonglong2*)(wb + (size_t)ci2 * 256 + 2);
#pragma unroll
                for (int p = 0; p < 8; p++) {
                    ffma2(acc[p][0], v[p], wA.x);
                    ffma2(acc[p][1], v[p], wA.y);
                    ffma2(acc[p][2], v[p], wB.x);
                    ffma2(acc[p][3], v[p], wB.y);
                }
            }
        }
    }
    int y = y0 + ry;
    float4 bb = *(const float4*)(b2 + co4 * 4);
#pragma unroll
    for (int p = 0; p < 8; p++) {
        float4 o;
        o.x = fmaxf(f2sum(acc[p][0]) + bb.x, 0.f);
        o.y = fmaxf(f2sum(acc[p][1]) + bb.y, 0.f);
        o.z = fmaxf(f2sum(acc[p][2]) + bb.z, 0.f);
        o.w = fmaxf(f2sum(acc[p][3]) + bb.w, 0.f);
        *(float4*)(g_feat + ((size_t)(b * 128 + y) * 128 + (x0 + p)) * 256 + co4 * 4) = o;
    }
}

// ---------------- detection heads: ci-pair packed; all 3 outputs share feature loads ----------------
__global__ void heads_kernel(const float* __restrict__ bsc, const float* __restrict__ brg) {
    int b = blockIdx.y;
    int warp = threadIdx.x >> 5, lane = threadIdx.x & 31;
    int p = blockIdx.x * 8 + warp;
    int y = p >> 7, x = p & 127;
    u64 aS = 0ull, aY = 0ull, aX = 0ull;
    const u64* whd = (const u64*)g_wt_h;
#pragma unroll
    for (int ky = 0; ky < 3; ky++) {
        int iy = y + ky - 1; if ((unsigned)iy >= 128u) continue;
#pragma unroll
        for (int kx = 0; kx < 3; kx++) {
            int ix = x + kx - 1; if ((unsigned)ix >= 128u) continue;
            const u64* fp = (const u64*)(g_feat + ((size_t)(b * 128 + iy) * 128 + ix) * 256);
            const u64* wp = whd + (ky * 3 + kx) * 128 * 3;
#pragma unroll
            for (int q = 0; q < 4; q++) {
                int ci2 = lane + q * 32;
                u64 f = fp[ci2];
                ffma2(aS, f, __ldg(wp + ci2 * 3));
                ffma2(aY, f, __ldg(wp + ci2 * 3 + 1));
                ffma2(aX, f, __ldg(wp + ci2 * 3 + 2));
            }
        }
    }
    float as = f2sum(aS), ay = f2sum(aY), ax = f2sum(aX);
#pragma unroll
    for (int o = 16; o > 0; o >>= 1) {
        as += __shfl_down_sync(~0u, as, o);
        ay += __shfl_down_sync(~0u, ay, o);
        ax += __shfl_down_sync(~0u, ax, o);
    }
    if (lane == 0) {
        g_scores[b * 16384 + p] = sigmoidf(as + __ldg(bsc));
        g_reg[(b * 16384 + p) * 2]     = ay + __ldg(brg);
        g_reg[(b * 16384 + p) * 2 + 1] = ax + __ldg(brg + 1);
    }
}

// ---------------- fused seg (1x1 256->256 relu) + segr (1x1 256->32 relu); ci-pair packed ----------------
__global__ void __launch_bounds__(256, 2) segseg_kernel(const float* __restrict__ bseg,
                                                        const float* __restrict__ br) {
    __shared__ __align__(16) float sf[32 * 256];
    int b = blockIdx.y; int p0 = blockIdx.x * 32; int t = threadIdx.x;
    {
        const float4* src = (const float4*)(g_feat + ((size_t)b * 16384 + p0) * 256);
        float4* dst4 = (float4*)sf;
        for (int e = t; e < 2048; e += 256) dst4[e] = src[e];
    }
    __syncthreads();
    int cg = t & 63, pg = t >> 6;
    int c0 = cg * 4;
    const float* sbase = sf + pg * 8 * 256;
    u64 acc[8][4];
#pragma unroll
    for (int p = 0; p < 8; p++)
#pragma unroll
        for (int j = 0; j < 4; j++) acc[p][j] = 0ull;
    const u64* wtd = (const u64*)g_wt_seg + c0;
    for (int ci2 = 0; ci2 < 128; ci2++) {
        u64 v[8];
#pragma unroll
        for (int p = 0; p < 8; p++) v[p] = *(const u64*)(sbase + p * 256 + 2 * ci2);
        ulonglong2 wA = *(const ulonglong2*)(wtd + (size_t)ci2 * 256);
        ulonglong2 wB = *(const ulonglong2*)(wtd + (size_t)ci2 * 256 + 2);
#pragma unroll
        for (int p = 0; p < 8; p++) {
            ffma2(acc[p][0], v[p], wA.x);
            ffma2(acc[p][1], v[p], wA.y);
            ffma2(acc[p][2], v[p], wB.x);
            ffma2(acc[p][3], v[p], wB.y);
        }
    }
    float bs[4];
#pragma unroll
    for (int j = 0; j < 4; j++) bs[j] = __ldg(bseg + c0 + j);
    __syncthreads();
#pragma unroll
    for (int p = 0; p < 8; p++) {
        float4 o;
        o.x = fmaxf(f2sum(acc[p][0]) + bs[0], 0.f);
        o.y = fmaxf(f2sum(acc[p][1]) + bs[1], 0.f);
        o.z = fmaxf(f2sum(acc[p][2]) + bs[2], 0.f);
        o.w = fmaxf(f2sum(acc[p][3]) + bs[3], 0.f);
        *(float4*)(sf + (pg * 8 + p) * 256 + c0) = o;
    }
    __syncthreads();
    int co = t & 31, pg2 = t >> 5;
    u64 a2[4];
#pragma unroll
    for (int q = 0; q < 4; q++) a2[q] = 0ull;
    const u64* wrd = (const u64*)g_wt_r + co;
    const float* s2 = sf + pg2 * 4 * 256;
    for (int ci2 = 0; ci2 < 128; ci2++) {
        u64 w = wrd[ci2 * 32];
#pragma unroll
        for (int q = 0; q < 4; q++)
            ffma2(a2[q], *(const u64*)(s2 + q * 256 + 2 * ci2), w);
    }
    float bc = __ldg(br + co);
#pragma unroll
    for (int q = 0; q < 4; q++)
        g_segr[((size_t)b * 16384 + p0 + pg2 * 4 + q) * 32 + co] = fmaxf(f2sum(a2[q]) + bc, 0.f);
}

// ---------------- top-K_PRE: full bitonic sort of 16384 packed keys per batch ----------------
__global__ void topk_kernel() {
    extern __shared__ unsigned long long sk[];
    int b = blockIdx.x, t = threadIdx.x;
    for (int e = t; e < 16384; e += 1024) {
        unsigned fb = __float_as_uint(g_scores[b * 16384 + e]);
        sk[e] = ((unsigned long long)fb << 32) | (unsigned)(16383 - e);
    }
    for (unsigned k = 2; k <= 16384u; k <<= 1)
        for (unsigned j = k >> 1; j > 0; j >>= 1) {
            __syncthreads();
            for (unsigned e = t; e < 16384; e += 1024) {
                unsigned l = e ^ j;
                if (l > e) {
                    unsigned long long A = sk[e], C = sk[l];
                    bool desc = ((e & k) == 0);
                    if ((A < C) == desc) { sk[e] = C; sk[l] = A; }
                }
            }
        }
    __syncthreads();
    for (int e = t; e < KPRE; e += 1024) {
        unsigned long long key = sk[e];
        float s = __uint_as_float((unsigned)(key >> 32));
        int idx = 16383 - (int)(unsigned)(key & 0xFFFFFFFFu);
        g_topsc[b * KPRE + e] = s;
        float yy = (float)(idx >> 7), xx = (float)(idx & 127);
        g_locs[(b * KPRE + e) * 2]     = yy + 0.5f + g_reg[(b * 16384 + idx) * 2];
        g_locs[(b * KPRE + e) * 2 + 1] = xx + 0.5f + g_reg[(b * 16384 + idx) * 2 + 1];
    }
}

// ---------------- suppression bitmatrix: smem-staged transposed locs (conflict-free) ----------------
__global__ void sup_kernel() {
    __shared__ float sy[32 * 65];
    __shared__ float sx[32 * 65];
    int i = blockIdx.x, b = blockIdx.y, t = threadIdx.x;   // 64 threads
    for (int j = t; j < KPRE; j += 64) {
        float2 lj = *(const float2*)(g_locs + (b * KPRE + j) * 2);
        sy[(j & 31) * 65 + (j >> 5)] = lj.x;
        sx[(j & 31) * 65 + (j >> 5)] = lj.y;
    }
    __syncthreads();
    float ly = g_locs[(b * KPRE + i) * 2], lx = g_locs[(b * KPRE + i) * 2 + 1];
    unsigned bits = 0;
    if (t < 63) {
#pragma unroll 4
        for (int u = 0; u < 32; u++) {
            int j = t * 32 + u;
            if (j < KPRE) {
                float dy = ly - sy[u * 65 + t];
                float dx = lx - sx[u * 65 + t];
                if (sqrtf(dy * dy + dx * dx) <= 1.1f) bits |= (1u << u);
            }
        }
    }
    g_sup[((size_t)(b * KPRE) + i) * 64 + t] = bits;
}

// ---------------- sequential greedy NMS scan (single warp/batch, deep prefetch) ----------------
__global__ void nms_scan_kernel() {
    int b = blockIdx.x, lane = threadIdx.x;   // 32 threads
    __shared__ unsigned ssup[64];
    __shared__ int slist[KOUT];
    ssup[lane] = 0; ssup[lane + 32] = 0;
    __syncwarp();
    const unsigned* base = g_sup + (size_t)b * KPRE * 64;
    unsigned ca[8], cb[8], na[8], nb[8];
#pragma unroll
    for (int u = 0; u < 8; u++) {
        ca[u] = base[(size_t)u * 64 + lane];
        cb[u] = (lane < 31) ? base[(size_t)u * 64 + 32 + lane] : 0u;
    }
    int cnt = 0;
    for (int ch = 0; ch < KPRE; ch += 8) {
        if (ch + 8 < KPRE) {
#pragma unroll
            for (int u = 0; u < 8; u++) {
                int i = ch + 8 + u;
                na[u] = base[(size_t)i * 64 + lane];
                nb[u] = (lane < 31) ? base[(size_t)i * 64 + 32 + lane] : 0u;
            }
        }
#pragma unroll
        for (int u = 0; u < 8; u++) {
            int i = ch + u;
            bool kp = ((ssup[i >> 5] >> (i & 31)) & 1u) == 0u;
            if (kp) {
                ssup[lane] |= ca[u];
                if (lane < 31) ssup[32 + lane] |= cb[u];
                if (lane == 0) { if (cnt < KOUT) slist[cnt] = i; cnt++; }
            }
            __syncwarp();
        }
#pragma unroll
        for (int u = 0; u < 8; u++) { ca[u] = na[u]; cb[u] = nb[u]; }
    }
    cnt = __shfl_sync(~0u, cnt, 0);
    if (lane == 0) g_nsel[b] = cnt;
    __syncwarp();
    int n = cnt < KOUT ? cnt : KOUT;
    for (int k = lane; k < n; k += 32) g_sel[b * KOUT + k] = slist[k];
}

// ---------------- selection: sel_s, pix outputs + crop top-lefts ----------------
__global__ void select_kernel(float* __restrict__ out) {
    int b = blockIdx.x; int k = threadIdx.x;
    if (k >= KOUT) return;
    int n = g_nsel[b]; if (n > KOUT) n = KOUT;
    bool valid = (k < n);
    float s = -1.f, ly = 0.f, lx = 0.f;
    if (valid) {
        int i = g_sel[b * KOUT + k];
        s  = g_topsc[b * KPRE + i];
        ly = g_locs[(b * KPRE + i) * 2];
        lx = g_locs[(b * KPRE + i) * 2 + 1];
    }
    float cy, cx;
    int o = b * KOUT + k;
    if (valid) {
        out[o] = s;
        out[2000 + o * 2]     = ly * 4.f;
        out[2000 + o * 2 + 1] = lx * 4.f;
        cy = ly; cx = lx;
    } else {
        out[o] = -1.f;
        out[2000 + o * 2] = -1.f;
        out[2000 + o * 2 + 1] = -1.f;
        cy = -0.25f; cx = -0.25f;    // pix=-1 -> (-1/512)*128
    }
    int ty = (int)rintf(cy) - 16; ty = min(max(ty, 0), 96);
    int tx = (int)rintf(cx) - 16; tx = min(max(tx, 0), 96);
    g_tl[o * 2] = ty; g_tl[o * 2 + 1] = tx;
}

// ---------------- inst_full: 4 px per warp, vectorized .128 loads, co-major weights ----------------
__global__ void instfull_kernel(const float* __restrict__ bp1v,
                                const float* __restrict__ wp2, const float* __restrict__ bp2v) {
    int t = threadIdx.x;
    int b = blockIdx.y;
    int wi = t >> 5, lane = t & 31;
    int g = blockIdx.x * 8 + wi;           // 4096 groups of 4 pixels
    int y = g >> 5, x0 = (g & 31) * 4;
    u64 acc[4];
#pragma unroll
    for (int p = 0; p < 4; p++) acc[p] = 0ull;
#pragma unroll
    for (int dy = -1; dy <= 1; dy++) {
        int iy = y + dy; if ((unsigned)iy >= 128u) continue;
#pragma unroll
        for (int dx = -1; dx <= 1; dx++) {
            int tap = (dy + 1) * 3 + (dx + 1);
            const ulonglong2* wv = (const ulonglong2*)g_wt_pc + ((size_t)tap * 32 + lane) * 8;
            ulonglong2 w[8];
#pragma unroll
            for (int i = 0; i < 8; i++) w[i] = __ldg(wv + i);
#pragma unroll
            for (int p = 0; p < 4; p++) {
                int ix = x0 + p + dx; if ((unsigned)ix >= 128u) continue;
                const ulonglong2* sp = (const ulonglong2*)(g_segr + ((size_t)(b * 128 + iy) * 128 + ix) * 32);
#pragma unroll
                for (int i = 0; i < 8; i++) {
                    ulonglong2 s = __ldg(sp + i);
                    ffma2(acc[p], s.x, w[i].x);
                    ffma2(acc[p], s.y, w[i].y);
                }
            }
        }
    }
    float b1l = __ldg(bp1v + lane), w2l = __ldg(wp2 + lane);
    float bp2s = __ldg(bp2v);
#pragma unroll
    for (int p = 0; p < 4; p++) {
        int x = x0 + p;
        float a = f2sum(acc[p]);
        g_acc1[((size_t)(b * 128 + y) * 128 + x) * 32 + lane] = a;
        float h = fmaxf(a + b1l, 0.f);
        float v = h * w2l;
#pragma unroll
        for (int o = 16; o > 0; o >>= 1) v += __shfl_down_sync(~0u, v, o);
        if (lane == 0) g_instfull[(size_t)(b * 128 + y) * 128 + x] = sigmoidf(v + bp2s);
    }
}

// ---------------- per-patch: gather interior; border via acc1 subtraction; .128 loads ----------------
__global__ void patch_kernel(const float* __restrict__ bp1v,
                             const float* __restrict__ wp2, const float* __restrict__ bp2v,
                             float* __restrict__ out) {
    int blk = blockIdx.x; int b = blk / KOUT, k = blk % KOUT;
    int t = threadIdx.x;
    int ty = g_tl[(b * KOUT + k) * 2], tx = g_tl[(b * KOUT + k) * 2 + 1];
    float* obase = out + 6000 + ((size_t)(b * KOUT + k)) * 1024;
    for (int e = t; e < 1024; e += 256) {
        int py = e >> 5, px = e & 31;
        if (py >= 1 && py <= 30 && px >= 1 && px <= 30)
            obase[e] = g_instfull[(size_t)(b * 128 + ty + py) * 128 + tx + px];
    }
    float bp2s = __ldg(bp2v);
    int warp = t >> 5, lane = t & 31;
    float sb1l = __ldg(bp1v + lane);
    float sw2l = __ldg(wp2 + lane);
    for (int bp = warp; bp < 124; bp += 8) {
        int py, px;
        if (bp < 32)      { py = 0;       px = bp; }
        else if (bp < 64) { py = 31;      px = bp - 32; }
        else if (bp < 94) { py = bp - 63; px = 0; }
        else              { py = bp - 93; px = 31; }
        int gy = ty + py, gx = tx + px;
        u64 corr = 0ull;
#pragma unroll
        for (int dy = -1; dy <= 1; dy++) {
            int ly = py + dy, yy = gy + dy;
#pragma unroll
            for (int dx = -1; dx <= 1; dx++) {
                int lx = px + dx, xx = gx + dx;
                bool outside_patch = ((unsigned)ly >= 32u) || ((unsigned)lx >= 32u);
                bool inside_global = ((unsigned)yy < 128u) && ((unsigned)xx < 128u);
                if (outside_patch && inside_global) {
                    int tap = (dy + 1) * 3 + (dx + 1);
                    const ulonglong2* wv = (const ulonglong2*)g_wt_pc + ((size_t)tap * 32 + lane) * 8;
                    const ulonglong2* sp = (const ulonglong2*)(g_segr + ((size_t)(b * 128 + yy) * 128 + xx) * 32);
#pragma unroll
                    for (int i = 0; i < 8; i++) {
                        ulonglong2 s = __ldg(sp + i);
                        ulonglong2 w = __ldg(wv + i);
                        ffma2(corr, s.x, w.x);
                        ffma2(corr, s.y, w.y);
                    }
                }
            }
        }
        float a = g_acc1[((size_t)(b * 128 + gy) * 128 + gx) * 32 + lane] - f2sum(corr);
        float h = fmaxf(a + sb1l, 0.f);
        float v = h * sw2l;
#pragma unroll
        for (int o = 16; o > 0; o >>= 1) v += __shfl_down_sync(~0u, v, o);
        if (lane == 0) obase[py * 32 + px] = sigmoidf(v + bp2s);
    }
}

// ---------------- launch ----------------
extern "C" void kernel_launch(void* const* d_in, const int* in_sizes, int n_in,
                              void* d_out, int out_size) {
    const float* image = (const float*)d_in[0];
    const float* w1   = (const float*)d_in[1];
    const float* b1   = (const float*)d_in[2];
    const float* w2   = (const float*)d_in[3];
    const float* b2   = (const float*)d_in[4];
    const float* wseg = (const float*)d_in[5];
    const float* bseg = (const float*)d_in[6];
    const float* wsc  = (const float*)d_in[7];
    const float* bsc  = (const float*)d_in[8];
    const float* wrg  = (const float*)d_in[9];
    const float* brg  = (const float*)d_in[10];
    const float* wr   = (const float*)d_in[11];
    const float* br   = (const float*)d_in[12];
    const float* wp1  = (const float*)d_in[13];
    const float* bp1  = (const float*)d_in[14];
    const float* wp2  = (const float*)d_in[15];
    const float* bp2  = (const float*)d_in[16];
    float* out = (float*)d_out;

    cudaFuncSetAttribute(topk_kernel, cudaFuncAttributeMaxDynamicSharedMemorySize, 131072);

    tr_all_kernel<<<927, 256>>>(wseg, wr, w2, wsc, wrg, wp1);

    conv1_kernel<<<dim3(32, 32, 4), 256>>>(image, w1, b1);
    conv2_kernel<<<dim3(16, 32, 4), 256>>>(b2);
    heads_kernel<<<dim3(2048, 4), 256>>>(bsc, brg);
    segseg_kernel<<<dim3(512, 4), 256>>>(bseg, br);
    topk_kernel<<<4, 1024, 131072>>>();
    sup_kernel<<<dim3(KPRE, 4), 64>>>();
    nms_scan_kernel<<<4, 32>>>();
    select_kernel<<<4, 512>>>(out);
    instfull_kernel<<<dim3(512, 4), 256>>>(bp1, wp2, bp2);
    patch_kernel<<<BB * KOUT, 256>>>(bp1, wp2, bp2, out);
}

// round 14
// speedup vs baseline: 1.4229x; 1.4229x over previous
#include <cuda_runtime.h>
#include <math.h>

// ---------------- constants ----------------
#define BB 4
#define HFD 128
#define WFD 128
#define KPRE 2000
#define KOUT 500

typedef unsigned long long u64;

// ---------------- scratch (device globals; no allocation allowed) ----------------
__device__ __align__(16) float g_x1[(size_t)4 * 256 * 256 * 64];       // conv1 out
__device__ __align__(16) float g_feat[(size_t)4 * 128 * 128 * 256];    // conv2 out
__device__ __align__(16) float g_segr[(size_t)4 * 128 * 128 * 32];     // reduced seg feats
__device__ __align__(16) float g_scores[4 * 16384];
__device__ __align__(16) float g_reg[4 * 16384 * 2];
__device__ __align__(16) float g_topsc[4 * KPRE];
__device__ __align__(16) float g_locs[4 * KPRE * 2];
__device__ __align__(16) unsigned g_sup[(size_t)4 * KPRE * 64];        // suppression bitmatrix
__device__ int g_sel[4 * KOUT];
__device__ int g_nsel[4];
__device__ int g_tl[4 * KOUT * 2];
__device__ __align__(16) float g_instfull[4 * 128 * 128];
__device__ __align__(16) float g_acc1[(size_t)4 * 128 * 128 * 32];     // instfull pre-bias acc

// transposed/interleaved weights for f32x2 (built per launch by one tiny kernel)
__device__ __align__(16) float g_wt_seg[256 * 256];   // [ci2][c][2]
__device__ __align__(16) float g_wt_r[256 * 32];      // [ci2][co][2]
__device__ __align__(16) float g_wt2[9 * 64 * 256];   // [tap][ci2][co][2]
__device__ __align__(16) float g_wt_hs[9 * 128 * 2];  // score head  [tap][ci2][2]
__device__ __align__(16) float g_wt_hy[9 * 128 * 2];  // reg-y head  [tap][ci2][2]
__device__ __align__(16) float g_wt_hx[9 * 128 * 2];  // reg-x head  [tap][ci2][2]
__device__ __align__(16) float g_wt_p1[9 * 16 * 64];  // [tap][ci2][co][2] (lane-consecutive u64)

__device__ __forceinline__ float sigmoidf(float z) { return 1.f / (1.f + expf(-z)); }

// ---- packed f32x2 helpers (u64 as b64 carrier of two floats; "l" constraints) ----
__device__ __forceinline__ void ffma2(u64& acc, u64 a, u64 b) {
    asm("fma.rn.f32x2 %0, %1, %2, %0;" : "+l"(acc) : "l"(a), "l"(b));
}
__device__ __forceinline__ u64 pack2(float v) {
    u64 d; asm("mov.b64 %0, {%1, %1};" : "=l"(d) : "f"(v)); return d;
}
__device__ __forceinline__ float f2sum(u64 a) {
    float lo, hi; asm("mov.b64 {%0, %1}, %2;" : "=f"(lo), "=f"(hi) : "l"(a));
    return lo + hi;
}
__device__ __forceinline__ void f2unpack(u64 a, float& lo, float& hi) {
    asm("mov.b64 {%0, %1}, %2;" : "=f"(lo), "=f"(hi) : "l"(a));
}

// ---------------- merged weight transpose kernel (one launch) ----------------
__global__ void tr_all_kernel(const float* __restrict__ wseg, const float* __restrict__ wr,
                              const float* __restrict__ w2, const float* __restrict__ wsc,
                              const float* __restrict__ wrg, const float* __restrict__ wp1) {
    int idx = blockIdx.x * 256 + threadIdx.x;
    if (idx < 65536) {
        int k = idx & 1, c = (idx >> 1) & 255, ci2 = idx >> 9;
        g_wt_seg[idx] = wseg[(2 * ci2 + k) * 256 + c];
    } else if (idx < 73728) {
        int rel = idx - 65536;
        int k = rel & 1, co = (rel >> 1) & 31, ci2 = rel >> 6;
        g_wt_r[rel] = wr[(2 * ci2 + k) * 32 + co];
    } else if (idx < 221184) {
        int rel = idx - 73728;
        int k = rel & 1, co = (rel >> 1) & 255;
        int r = rel >> 9; int ci2 = r & 31; int tap = r >> 5;
        g_wt2[rel] = w2[(tap * 64 + 2 * ci2 + k) * 256 + co];
    } else if (idx < 223488) {
        int rel = idx - 221184;                    // score head
        int k = rel & 1, ci2 = (rel >> 1) & 127, tap = rel >> 8;
        g_wt_hs[rel] = wsc[tap * 256 + 2 * ci2 + k];
    } else if (idx < 225792) {
        int rel = idx - 223488;                    // reg-y head
        int k = rel & 1, ci2 = (rel >> 1) & 127, tap = rel >> 8;
        g_wt_hy[rel] = wrg[(tap * 256 + 2 * ci2 + k) * 2];
    } else if (idx < 228096) {
        int rel = idx - 225792;                    // reg-x head
        int k = rel & 1, ci2 = (rel >> 1) & 127, tap = rel >> 8;
        g_wt_hx[rel] = wrg[(tap * 256 + 2 * ci2 + k) * 2 + 1];
    } else if (idx < 237312) {
        int rel = idx - 228096;                    // [tap][ci2][co][2]
        int kk = rel & 1, co = (rel >> 1) & 31, r = rel >> 6;
        int ci2 = r & 15, tap = r >> 4;
        g_wt_p1[rel] = wp1[(tap * 32 + 2 * ci2 + kk) * 32 + co];
    }
}

// ---------------- conv1: 3x3 s2, 3->64, relu (SAME => iy=2y+ky, pad_lo=0) ----------------
__global__ void conv1_kernel(const float* __restrict__ img, const float* __restrict__ w1,
                             const float* __restrict__ b1) {
    __shared__ __align__(16) float smimg[17 * 17 * 3 + 1];
    __shared__ __align__(16) float wsh[27 * 64];
    __shared__ __align__(16) float sbias[64];
    int x0 = blockIdx.x * 8, y0 = blockIdx.y * 8, b = blockIdx.z;
    int t = threadIdx.x;
    for (int e = t; e < 17 * 17 * 3; e += 256) {
        int r = e / 51, rem = e % 51, c = rem / 3, ci = rem % 3;
        int iy = 2 * y0 + r, ix = 2 * x0 + c;
        smimg[e] = (iy < 512 && ix < 512) ? __ldg(img + ((size_t)(b * 512 + iy) * 512 + ix) * 3 + ci) : 0.f;
    }
    for (int e = t; e < 27 * 64; e += 256) wsh[e] = __ldg(w1 + e);
    if (t < 64) sbias[t] = __ldg(b1 + t);
    __syncthreads();
    int copair = t & 31, py = t >> 5;
    int c0 = copair * 2;
    u64 acc[8];
#pragma unroll
    for (int p = 0; p < 8; p++) acc[p] = 0ull;
#pragma unroll
    for (int ky = 0; ky < 3; ky++) {
        int rowb = (2 * py + ky) * 51;
#pragma unroll
        for (int kx = 0; kx < 3; kx++) {
#pragma unroll
            for (int ci = 0; ci < 3; ci++) {
                u64 w2v = *(const u64*)(wsh + ((ky * 3 + kx) * 3 + ci) * 64 + c0);
                int off = rowb + kx * 3 + ci;
#pragma unroll
                for (int p = 0; p < 8; p++) {
                    u64 vv = pack2(smimg[off + p * 6]);
                    ffma2(acc[p], vv, w2v);
                }
            }
        }
    }
    float2 bb = *(const float2*)(sbias + c0);
    int y = y0 + py;
#pragma unroll
    for (int p = 0; p < 8; p++) {
        float lo, hi; f2unpack(acc[p], lo, hi);
        float2 o;
        o.x = fmaxf(lo + bb.x, 0.f);
        o.y = fmaxf(hi + bb.y, 0.f);
        *(float2*)(g_x1 + ((size_t)(b * 256 + y) * 256 + (x0 + p)) * 64 + c0) = o;
    }
}

// ---------------- conv2: 3x3 s2, 64->256, relu; ci-pair packed ----------------
__global__ void __launch_bounds__(256, 2) conv2_kernel(const float* __restrict__ b2) {
    __shared__ __align__(16) float sm[9 * 17 * 64];
    int x0 = blockIdx.x * 8, y0 = blockIdx.y * 4, b = blockIdx.z;
    int t = threadIdx.x;
    for (int e = t; e < 9 * 17 * 64; e += 256) {
        int ci = e & 63; int rc = e >> 6; int c = rc % 17; int r = rc / 17;
        int iy = 2 * y0 + r, ix = 2 * x0 + c;
        float v = 0.f;
        if (iy < 256 && ix < 256) v = g_x1[((size_t)(b * 256 + iy) * 256 + ix) * 64 + ci];
        sm[e] = v;
    }
    __syncthreads();
    int co4 = t & 63, ry = t >> 6;
    u64 acc[8][4];
#pragma unroll
    for (int p = 0; p < 8; p++)
#pragma unroll
        for (int j = 0; j < 4; j++) acc[p][j] = 0ull;
    const u64* wt2d = (const u64*)g_wt2;
#pragma unroll
    for (int ky = 0; ky < 3; ky++) {
        int r = 2 * ry + ky;
#pragma unroll
        for (int kx = 0; kx < 3; kx++) {
            const float* sbase = sm + (r * 17 + kx) * 64;
            const u64* wb = wt2d + (size_t)((ky * 3 + kx) * 32) * 256 + co4 * 4;
            for (int ci2 = 0; ci2 < 32; ci2++) {
                u64 v[8];
#pragma unroll
                for (int p = 0; p < 8; p++) v[p] = *(const u64*)(sbase + p * 128 + 2 * ci2);
                ulonglong2 wA = *(const ulonglong2*)(wb + (size_t)ci2 * 256);
                ulonglong2 wB = *(const ulonglong2*)(wb + (size_t)ci2 * 256 + 2);
#pragma unroll
                for (int p = 0; p < 8; p++) {
                    ffma2(acc[p][0], v[p], wA.x);
                    ffma2(acc[p][1], v[p], wA.y);
                    ffma2(acc[p][2], v[p], wB.x);
                    ffma2(acc[p][3], v[p], wB.y);
                }
            }
        }
    }
    int y = y0 + ry;
    float4 bb = *(const float4*)(b2 + co4 * 4);
#pragma unroll
    for (int p = 0; p < 8; p++) {
        float4 o;
        o.x = fmaxf(f2sum(acc[p][0]) + bb.x, 0.f);
        o.y = fmaxf(f2sum(acc[p][1]) + bb.y, 0.f);
        o.z = fmaxf(f2sum(acc[p][2]) + bb.z, 0.f);
        o.w = fmaxf(f2sum(acc[p][3]) + bb.w, 0.f);
        *(float4*)(g_feat + ((size_t)(b * 128 + y) * 128 + (x0 + p)) * 256 + co4 * 4) = o;
    }
}

// ---------------- detection heads: split lane-consecutive weight tables ----------------
__global__ void heads_kernel(const float* __restrict__ bsc, const float* __restrict__ brg) {
    int b = blockIdx.y;
    int warp = threadIdx.x >> 5, lane = threadIdx.x & 31;
    int p = blockIdx.x * 8 + warp;
    int y = p >> 7, x = p & 127;
    u64 aS = 0ull, aY = 0ull, aX = 0ull;
#pragma unroll
    for (int ky = 0; ky < 3; ky++) {
        int iy = y + ky - 1; if ((unsigned)iy >= 128u) continue;
#pragma unroll
        for (int kx = 0; kx < 3; kx++) {
            int ix = x + kx - 1; if ((unsigned)ix >= 128u) continue;
            int tap = ky * 3 + kx;
            const u64* fp = (const u64*)(g_feat + ((size_t)(b * 128 + iy) * 128 + ix) * 256);
            const u64* wS = (const u64*)g_wt_hs + tap * 128;
            const u64* wY = (const u64*)g_wt_hy + tap * 128;
            const u64* wX = (const u64*)g_wt_hx + tap * 128;
#pragma unroll
            for (int q = 0; q < 4; q++) {
                int ci2 = lane + q * 32;
                u64 f = fp[ci2];
                ffma2(aS, f, __ldg(wS + ci2));
                ffma2(aY, f, __ldg(wY + ci2));
                ffma2(aX, f, __ldg(wX + ci2));
            }
        }
    }
    float as = f2sum(aS), ay = f2sum(aY), ax = f2sum(aX);
#pragma unroll
    for (int o = 16; o > 0; o >>= 1) {
        as += __shfl_down_sync(~0u, as, o);
        ay += __shfl_down_sync(~0u, ay, o);
        ax += __shfl_down_sync(~0u, ax, o);
    }
    if (lane == 0) {
        g_scores[b * 16384 + p] = sigmoidf(as + __ldg(bsc));
        g_reg[(b * 16384 + p) * 2]     = ay + __ldg(brg);
        g_reg[(b * 16384 + p) * 2 + 1] = ax + __ldg(brg + 1);
    }
}

// ---------------- fused seg (1x1 256->256 relu) + segr (1x1 256->32 relu); ci-pair packed ----------------
__global__ void __launch_bounds__(256, 2) segseg_kernel(const float* __restrict__ bseg,
                                                        const float* __restrict__ br) {
    __shared__ __align__(16) float sf[32 * 256];
    int b = blockIdx.y; int p0 = blockIdx.x * 32; int t = threadIdx.x;
    {
        const float4* src = (const float4*)(g_feat + ((size_t)b * 16384 + p0) * 256);
        float4* dst4 = (float4*)sf;
        for (int e = t; e < 2048; e += 256) dst4[e] = src[e];
    }
    __syncthreads();
    int cg = t & 63, pg = t >> 6;
    int c0 = cg * 4;
    const float* sbase = sf + pg * 8 * 256;
    u64 acc[8][4];
#pragma unroll
    for (int p = 0; p < 8; p++)
#pragma unroll
        for (int j = 0; j < 4; j++) acc[p][j] = 0ull;
    const u64* wtd = (const u64*)g_wt_seg + c0;
    for (int ci2 = 0; ci2 < 128; ci2++) {
        u64 v[8];
#pragma unroll
        for (int p = 0; p < 8; p++) v[p] = *(const u64*)(sbase + p * 256 + 2 * ci2);
        ulonglong2 wA = *(const ulonglong2*)(wtd + (size_t)ci2 * 256);
        ulonglong2 wB = *(const ulonglong2*)(wtd + (size_t)ci2 * 256 + 2);
#pragma unroll
        for (int p = 0; p < 8; p++) {
            ffma2(acc[p][0], v[p], wA.x);
            ffma2(acc[p][1], v[p], wA.y);
            ffma2(acc[p][2], v[p], wB.x);
            ffma2(acc[p][3], v[p], wB.y);
        }
    }
    float bs[4];
#pragma unroll
    for (int j = 0; j < 4; j++) bs[j] = __ldg(bseg + c0 + j);
    __syncthreads();
#pragma unroll
    for (int p = 0; p < 8; p++) {
        float4 o;
        o.x = fmaxf(f2sum(acc[p][0]) + bs[0], 0.f);
        o.y = fmaxf(f2sum(acc[p][1]) + bs[1], 0.f);
        o.z = fmaxf(f2sum(acc[p][2]) + bs[2], 0.f);
        o.w = fmaxf(f2sum(acc[p][3]) + bs[3], 0.f);
        *(float4*)(sf + (pg * 8 + p) * 256 + c0) = o;
    }
    __syncthreads();
    int co = t & 31, pg2 = t >> 5;
    u64 a2[4];
#pragma unroll
    for (int q = 0; q < 4; q++) a2[q] = 0ull;
    const u64* wrd = (const u64*)g_wt_r + co;
    const float* s2 = sf + pg2 * 4 * 256;
    for (int ci2 = 0; ci2 < 128; ci2++) {
        u64 w = wrd[ci2 * 32];
#pragma unroll
        for (int q = 0; q < 4; q++)
            ffma2(a2[q], *(const u64*)(s2 + q * 256 + 2 * ci2), w);
    }
    float bc = __ldg(br + co);
#pragma unroll
    for (int q = 0; q < 4; q++)
        g_segr[((size_t)b * 16384 + p0 + pg2 * 4 + q) * 32 + co] = fmaxf(f2sum(a2[q]) + bc, 0.f);
}

// ---------------- top-K_PRE: full bitonic sort of 16384 packed keys per batch ----------------
__global__ void topk_kernel() {
    extern __shared__ unsigned long long sk[];
    int b = blockIdx.x, t = threadIdx.x;
    for (int e = t; e < 16384; e += 1024) {
        unsigned fb = __float_as_uint(g_scores[b * 16384 + e]);
        sk[e] = ((unsigned long long)fb << 32) | (unsigned)(16383 - e);
    }
    for (unsigned k = 2; k <= 16384u; k <<= 1)
        for (unsigned j = k >> 1; j > 0; j >>= 1) {
            __syncthreads();
            for (unsigned e = t; e < 16384; e += 1024) {
                unsigned l = e ^ j;
                if (l > e) {
                    unsigned long long A = sk[e], C = sk[l];
                    bool desc = ((e & k) == 0);
                    if ((A < C) == desc) { sk[e] = C; sk[l] = A; }
                }
            }
        }
    __syncthreads();
    for (int e = t; e < KPRE; e += 1024) {
        unsigned long long key = sk[e];
        float s = __uint_as_float((unsigned)(key >> 32));
        int idx = 16383 - (int)(unsigned)(key & 0xFFFFFFFFu);
        g_topsc[b * KPRE + e] = s;
        float yy = (float)(idx >> 7), xx = (float)(idx & 127);
        g_locs[(b * KPRE + e) * 2]     = yy + 0.5f + g_reg[(b * 16384 + idx) * 2];
        g_locs[(b * KPRE + e) * 2 + 1] = xx + 0.5f + g_reg[(b * 16384 + idx) * 2 + 1];
    }
}

// ---------------- suppression bitmatrix: 32 i-rows per block, staged once ----------------
__global__ void sup_kernel() {
    __shared__ float sy[32 * 65];
    __shared__ float sx[32 * 65];
    int b = blockIdx.y, i0 = blockIdx.x * 32, t = threadIdx.x;   // 256 threads
    for (int j = t; j < KPRE; j += 256) {
        float2 lj = *(const float2*)(g_locs + (b * KPRE + j) * 2);
        sy[(j & 31) * 65 + (j >> 5)] = lj.x;
        sx[(j & 31) * 65 + (j >> 5)] = lj.y;
    }
    __syncthreads();
    int wq = t & 63;
#pragma unroll
    for (int k = 0; k < 8; k++) {
        int il = (t >> 6) + k * 4;               // 0..31
        int i = i0 + il;
        if (i >= KPRE) continue;
        float ly = sy[(i & 31) * 65 + (i >> 5)];
        float lx = sx[(i & 31) * 65 + (i >> 5)];
        unsigned bits = 0;
        if (wq < 63) {
#pragma unroll 4
            for (int u = 0; u < 32; u++) {
                int j = wq * 32 + u;
                if (j < KPRE) {
                    float dy = ly - sy[u * 65 + wq];
                    float dx = lx - sx[u * 65 + wq];
                    if (sqrtf(dy * dy + dx * dx) <= 1.1f) bits |= (1u << u);
                }
            }
        }
        g_sup[((size_t)(b * KPRE) + i) * 64 + wq] = bits;
    }
}

// ---------------- sequential greedy NMS scan (single warp/batch, deep prefetch) ----------------
__global__ void nms_scan_kernel() {
    int b = blockIdx.x, lane = threadIdx.x;   // 32 threads
    __shared__ unsigned ssup[64];
    __shared__ int slist[KOUT];
    ssup[lane] = 0; ssup[lane + 32] = 0;
    __syncwarp();
    const unsigned* base = g_sup + (size_t)b * KPRE * 64;
    unsigned ca[8], cb[8], na[8], nb[8];
#pragma unroll
    for (int u = 0; u < 8; u++) {
        ca[u] = base[(size_t)u * 64 + lane];
        cb[u] = (lane < 31) ? base[(size_t)u * 64 + 32 + lane] : 0u;
    }
    int cnt = 0;
    for (int ch = 0; ch < KPRE; ch += 8) {
        if (ch + 8 < KPRE) {
#pragma unroll
            for (int u = 0; u < 8; u++) {
                int i = ch + 8 + u;
                na[u] = base[(size_t)i * 64 + lane];
                nb[u] = (lane < 31) ? base[(size_t)i * 64 + 32 + lane] : 0u;
            }
        }
#pragma unroll
        for (int u = 0; u < 8; u++) {
            int i = ch + u;
            bool kp = ((ssup[i >> 5] >> (i & 31)) & 1u) == 0u;
            if (kp) {
                ssup[lane] |= ca[u];
                if (lane < 31) ssup[32 + lane] |= cb[u];
                if (lane == 0) { if (cnt < KOUT) slist[cnt] = i; cnt++; }
            }
            __syncwarp();
        }
#pragma unroll
        for (int u = 0; u < 8; u++) { ca[u] = na[u]; cb[u] = nb[u]; }
    }
    cnt = __shfl_sync(~0u, cnt, 0);
    if (lane == 0) g_nsel[b] = cnt;
    __syncwarp();
    int n = cnt < KOUT ? cnt : KOUT;
    for (int k = lane; k < n; k += 32) g_sel[b * KOUT + k] = slist[k];
}

// ---------------- selection: sel_s, pix outputs + crop top-lefts ----------------
__global__ void select_kernel(float* __restrict__ out) {
    int b = blockIdx.x; int k = threadIdx.x;
    if (k >= KOUT) return;
    int n = g_nsel[b]; if (n > KOUT) n = KOUT;
    bool valid = (k < n);
    float s = -1.f, ly = 0.f, lx = 0.f;
    if (valid) {
        int i = g_sel[b * KOUT + k];
        s  = g_topsc[b * KPRE + i];
        ly = g_locs[(b * KPRE + i) * 2];
        lx = g_locs[(b * KPRE + i) * 2 + 1];
    }
    float cy, cx;
    int o = b * KOUT + k;
    if (valid) {
        out[o] = s;
        out[2000 + o * 2]     = ly * 4.f;
        out[2000 + o * 2 + 1] = lx * 4.f;
        cy = ly; cx = lx;
    } else {
        out[o] = -1.f;
        out[2000 + o * 2] = -1.f;
        out[2000 + o * 2 + 1] = -1.f;
        cy = -0.25f; cx = -0.25f;    // pix=-1 -> (-1/512)*128
    }
    int ty = (int)rintf(cy) - 16; ty = min(max(ty, 0), 96);
    int tx = (int)rintf(cx) - 16; tx = min(max(tx, 0), 96);
    g_tl[o * 2] = ty; g_tl[o * 2 + 1] = tx;
}

// ---------------- inst_full: 4 px/warp; lane-consecutive weights + broadcast .128 acts ----------------
__global__ void instfull_kernel(const float* __restrict__ bp1v,
                                const float* __restrict__ wp2, const float* __restrict__ bp2v) {
    int t = threadIdx.x;
    int b = blockIdx.y;
    int wi = t >> 5, lane = t & 31;
    int g = blockIdx.x * 8 + wi;           // 4096 groups of 4 pixels
    int y = g >> 5, x0 = (g & 31) * 4;
    const u64* wsd = (const u64*)g_wt_p1;  // [tap][ci2][co]
    u64 acc[4];
#pragma unroll
    for (int p = 0; p < 4; p++) acc[p] = 0ull;
#pragma unroll
    for (int dy = -1; dy <= 1; dy++) {
        int iy = y + dy; if ((unsigned)iy >= 128u) continue;
#pragma unroll
        for (int dx = -1; dx <= 1; dx++) {
            int tap = (dy + 1) * 3 + (dx + 1);
            const u64* wb = wsd + tap * 512 + lane;
            u64 w[16];
#pragma unroll
            for (int i = 0; i < 16; i++) w[i] = __ldg(wb + i * 32);
#pragma unroll
            for (int p = 0; p < 4; p++) {
                int ix = x0 + p + dx; if ((unsigned)ix >= 128u) continue;
                const ulonglong2* sp = (const ulonglong2*)(g_segr + ((size_t)(b * 128 + iy) * 128 + ix) * 32);
#pragma unroll
                for (int i = 0; i < 8; i++) {
                    ulonglong2 s = __ldg(sp + i);
                    ffma2(acc[p], s.x, w[2 * i]);
                    ffma2(acc[p], s.y, w[2 * i + 1]);
                }
            }
        }
    }
    float b1l = __ldg(bp1v + lane), w2l = __ldg(wp2 + lane);
    float bp2s = __ldg(bp2v);
#pragma unroll
    for (int p = 0; p < 4; p++) {
        int x = x0 + p;
        float a = f2sum(acc[p]);
        g_acc1[((size_t)(b * 128 + y) * 128 + x) * 32 + lane] = a;
        float h = fmaxf(a + b1l, 0.f);
        float v = h * w2l;
#pragma unroll
        for (int o = 16; o > 0; o >>= 1) v += __shfl_down_sync(~0u, v, o);
        if (lane == 0) g_instfull[(size_t)(b * 128 + y) * 128 + x] = sigmoidf(v + bp2s);
    }
}

// ---------------- per-patch: gather interior; border via acc1 subtraction ----------------
__global__ void patch_kernel(const float* __restrict__ bp1v,
                             const float* __restrict__ wp2, const float* __restrict__ bp2v,
                             float* __restrict__ out) {
    int blk = blockIdx.x; int b = blk / KOUT, k = blk % KOUT;
    int t = threadIdx.x;
    int ty = g_tl[(b * KOUT + k) * 2], tx = g_tl[(b * KOUT + k) * 2 + 1];
    float* obase = out + 6000 + ((size_t)(b * KOUT + k)) * 1024;
    for (int e = t; e < 1024; e += 256) {
        int py = e >> 5, px = e & 31;
        if (py >= 1 && py <= 30 && px >= 1 && px <= 30)
            obase[e] = g_instfull[(size_t)(b * 128 + ty + py) * 128 + tx + px];
    }
    float bp2s = __ldg(bp2v);
    int warp = t >> 5, lane = t & 31;
    const u64* wsd = (const u64*)g_wt_p1;
    float sb1l = __ldg(bp1v + lane);
    float sw2l = __ldg(wp2 + lane);
    for (int bp = warp; bp < 124; bp += 8) {
        int py, px;
        if (bp < 32)      { py = 0;       px = bp; }
        else if (bp < 64) { py = 31;      px = bp - 32; }
        else if (bp < 94) { py = bp - 63; px = 0; }
        else              { py = bp - 93; px = 31; }
        int gy = ty + py, gx = tx + px;
        u64 corr = 0ull;
#pragma unroll
        for (int dy = -1; dy <= 1; dy++) {
            int ly = py + dy, yy = gy + dy;
#pragma unroll
            for (int dx = -1; dx <= 1; dx++) {
                int lx = px + dx, xx = gx + dx;
                bool outside_patch = ((unsigned)ly >= 32u) || ((unsigned)lx >= 32u);
                bool inside_global = ((unsigned)yy < 128u) && ((unsigned)xx < 128u);
                if (outside_patch && inside_global) {
                    int tap = (dy + 1) * 3 + (dx + 1);
                    const u64* wb = wsd + tap * 512 + lane;
                    const ulonglong2* sp = (const ulonglong2*)(g_segr + ((size_t)(b * 128 + yy) * 128 + xx) * 32);
#pragma unroll
                    for (int i = 0; i < 8; i++) {
                        ulonglong2 s = __ldg(sp + i);
                        ffma2(corr, s.x, __ldg(wb + (2 * i) * 32));
                        ffma2(corr, s.y, __ldg(wb + (2 * i + 1) * 32));
                    }
                }
            }
        }
        float a = g_acc1[((size_t)(b * 128 + gy) * 128 + gx) * 32 + lane] - f2sum(corr);
        float h = fmaxf(a + sb1l, 0.f);
        float v = h * sw2l;
#pragma unroll
        for (int o = 16; o > 0; o >>= 1) v += __shfl_down_sync(~0u, v, o);
        if (lane == 0) obase[py * 32 + px] = sigmoidf(v + bp2s);
    }
}

// ---------------- launch ----------------
extern "C" void kernel_launch(void* const* d_in, const int* in_sizes, int n_in,
                              void* d_out, int out_size) {
    const float* image = (const float*)d_in[0];
    const float* w1   = (const float*)d_in[1];
    const float* b1   = (const float*)d_in[2];
    const float* w2   = (const float*)d_in[3];
    const float* b2   = (const float*)d_in[4];
    const float* wseg = (const float*)d_in[5];
    const float* bseg = (const float*)d_in[6];
    const float* wsc  = (const float*)d_in[7];
    const float* bsc  = (const float*)d_in[8];
    const float* wrg  = (const float*)d_in[9];
    const float* brg  = (const float*)d_in[10];
    const float* wr   = (const float*)d_in[11];
    const float* br   = (const float*)d_in[12];
    const float* wp1  = (const float*)d_in[13];
    const float* bp1  = (const float*)d_in[14];
    const float* wp2  = (const float*)d_in[15];
    const float* bp2  = (const float*)d_in[16];
    float* out = (float*)d_out;

    cudaFuncSetAttribute(topk_kernel, cudaFuncAttributeMaxDynamicSharedMemorySize, 131072);

    tr_all_kernel<<<927, 256>>>(wseg, wr, w2, wsc, wrg, wp1);

    conv1_kernel<<<dim3(32, 32, 4), 256>>>(image, w1, b1);
    conv2_kernel<<<dim3(16, 32, 4), 256>>>(b2);
    heads_kernel<<<dim3(2048, 4), 256>>>(bsc, brg);
    segseg_kernel<<<dim3(512, 4), 256>>>(bseg, br);
    topk_kernel<<<4, 1024, 131072>>>();
    sup_kernel<<<dim3(63, 4), 256>>>();
    nms_scan_kernel<<<4, 32>>>();
    select_kernel<<<4, 512>>>(out);
    instfull_kernel<<<dim3(512, 4), 256>>>(bp1, wp2, bp2);
    patch_kernel<<<BB * KOUT, 256>>>(bp1, wp2, bp2, out);
}

// round 15
// speedup vs baseline: 1.7192x; 1.2082x over previous
#include <cuda_runtime.h>
#include <math.h>

// ---------------- constants ----------------
#define BB 4
#define HFD 128
#define WFD 128
#define KPRE 2000
#define KOUT 500

typedef unsigned long long u64;

// ---------------- scratch (device globals; no allocation allowed) ----------------
__device__ __align__(16) float g_x1[(size_t)4 * 256 * 256 * 64];       // conv1 out
__device__ __align__(16) float g_feat[(size_t)4 * 128 * 128 * 256];    // conv2 out
__device__ __align__(16) float g_segr[(size_t)4 * 128 * 128 * 32];     // reduced seg feats
__device__ __align__(16) float g_scores[4 * 16384];
__device__ __align__(16) float g_reg[4 * 16384 * 2];
__device__ __align__(16) float g_topsc[4 * KPRE];
__device__ __align__(16) float g_locs[4 * KPRE * 2];
__device__ __align__(16) unsigned g_sup[(size_t)4 * KPRE * 64];        // suppression bitmatrix
__device__ int g_sel[4 * KOUT];
__device__ int g_nsel[4];
__device__ int g_tl[4 * KOUT * 2];
__device__ __align__(16) float g_instfull[4 * 128 * 128];
__device__ __align__(16) float g_acc1[(size_t)4 * 128 * 128 * 32];     // instfull pre-bias acc

// transposed/interleaved weights for f32x2 (built per launch by one tiny kernel)
__device__ __align__(16) float g_wt_seg[256 * 256];   // [ci2][c][2]
__device__ __align__(16) float g_wt_r[256 * 32];      // [ci2][co][2]
__device__ __align__(16) float g_wt2[9 * 64 * 256];   // [tap][ci2][co][2]
__device__ __align__(16) float g_wt_hs[9 * 128 * 2];  // score head  [tap][ci2][2]
__device__ __align__(16) float g_wt_hy[9 * 128 * 2];  // reg-y head  [tap][ci2][2]
__device__ __align__(16) float g_wt_hx[9 * 128 * 2];  // reg-x head  [tap][ci2][2]
__device__ __align__(16) float g_wt_p1[9 * 16 * 64];  // [tap][ci2][co][2] (lane-consecutive u64)

__device__ __forceinline__ float sigmoidf(float z) { return 1.f / (1.f + expf(-z)); }

// ---- packed f32x2 helpers (u64 as b64 carrier of two floats; "l" constraints) ----
__device__ __forceinline__ void ffma2(u64& acc, u64 a, u64 b) {
    asm("fma.rn.f32x2 %0, %1, %2, %0;" : "+l"(acc) : "l"(a), "l"(b));
}
__device__ __forceinline__ u64 pack2(float v) {
    u64 d; asm("mov.b64 %0, {%1, %1};" : "=l"(d) : "f"(v)); return d;
}
__device__ __forceinline__ float f2sum(u64 a) {
    float lo, hi; asm("mov.b64 {%0, %1}, %2;" : "=f"(lo), "=f"(hi) : "l"(a));
    return lo + hi;
}
__device__ __forceinline__ void f2unpack(u64 a, float& lo, float& hi) {
    asm("mov.b64 {%0, %1}, %2;" : "=f"(lo), "=f"(hi) : "l"(a));
}

// ---------------- merged weight transpose kernel (one launch) ----------------
__global__ void tr_all_kernel(const float* __restrict__ wseg, const float* __restrict__ wr,
                              const float* __restrict__ w2, const float* __restrict__ wsc,
                              const float* __restrict__ wrg, const float* __restrict__ wp1) {
    int idx = blockIdx.x * 256 + threadIdx.x;
    if (idx < 65536) {
        int k = idx & 1, c = (idx >> 1) & 255, ci2 = idx >> 9;
        g_wt_seg[idx] = wseg[(2 * ci2 + k) * 256 + c];
    } else if (idx < 73728) {
        int rel = idx - 65536;
        int k = rel & 1, co = (rel >> 1) & 31, ci2 = rel >> 6;
        g_wt_r[rel] = wr[(2 * ci2 + k) * 32 + co];
    } else if (idx < 221184) {
        int rel = idx - 73728;
        int k = rel & 1, co = (rel >> 1) & 255;
        int r = rel >> 9; int ci2 = r & 31; int tap = r >> 5;
        g_wt2[rel] = w2[(tap * 64 + 2 * ci2 + k) * 256 + co];
    } else if (idx < 223488) {
        int rel = idx - 221184;                    // score head
        int k = rel & 1, ci2 = (rel >> 1) & 127, tap = rel >> 8;
        g_wt_hs[rel] = wsc[tap * 256 + 2 * ci2 + k];
    } else if (idx < 225792) {
        int rel = idx - 223488;                    // reg-y head
        int k = rel & 1, ci2 = (rel >> 1) & 127, tap = rel >> 8;
        g_wt_hy[rel] = wrg[(tap * 256 + 2 * ci2 + k) * 2];
    } else if (idx < 228096) {
        int rel = idx - 225792;                    // reg-x head
        int k = rel & 1, ci2 = (rel >> 1) & 127, tap = rel >> 8;
        g_wt_hx[rel] = wrg[(tap * 256 + 2 * ci2 + k) * 2 + 1];
    } else if (idx < 237312) {
        int rel = idx - 228096;                    // [tap][ci2][co][2]
        int kk = rel & 1, co = (rel >> 1) & 31, r = rel >> 6;
        int ci2 = r & 15, tap = r >> 4;
        g_wt_p1[rel] = wp1[(tap * 32 + 2 * ci2 + kk) * 32 + co];
    }
}

// ---------------- conv1: 3x3 s2, 3->64, relu (SAME => iy=2y+ky, pad_lo=0) ----------------
__global__ void conv1_kernel(const float* __restrict__ img, const float* __restrict__ w1,
                             const float* __restrict__ b1) {
    __shared__ __align__(16) float smimg[17 * 17 * 3 + 1];
    __shared__ __align__(16) float wsh[27 * 64];
    __shared__ __align__(16) float sbias[64];
    int x0 = blockIdx.x * 8, y0 = blockIdx.y * 8, b = blockIdx.z;
    int t = threadIdx.x;
    for (int e = t; e < 17 * 17 * 3; e += 256) {
        int r = e / 51, rem = e % 51, c = rem / 3, ci = rem % 3;
        int iy = 2 * y0 + r, ix = 2 * x0 + c;
        smimg[e] = (iy < 512 && ix < 512) ? __ldg(img + ((size_t)(b * 512 + iy) * 512 + ix) * 3 + ci) : 0.f;
    }
    for (int e = t; e < 27 * 64; e += 256) wsh[e] = __ldg(w1 + e);
    if (t < 64) sbias[t] = __ldg(b1 + t);
    __syncthreads();
    int copair = t & 31, py = t >> 5;
    int c0 = copair * 2;
    u64 acc[8];
#pragma unroll
    for (int p = 0; p < 8; p++) acc[p] = 0ull;
#pragma unroll
    for (int ky = 0; ky < 3; ky++) {
        int rowb = (2 * py + ky) * 51;
#pragma unroll
        for (int kx = 0; kx < 3; kx++) {
#pragma unroll
            for (int ci = 0; ci < 3; ci++) {
                u64 w2v = *(const u64*)(wsh + ((ky * 3 + kx) * 3 + ci) * 64 + c0);
                int off = rowb + kx * 3 + ci;
#pragma unroll
                for (int p = 0; p < 8; p++) {
                    u64 vv = pack2(smimg[off + p * 6]);
                    ffma2(acc[p], vv, w2v);
                }
            }
        }
    }
    float2 bb = *(const float2*)(sbias + c0);
    int y = y0 + py;
#pragma unroll
    for (int p = 0; p < 8; p++) {
        float lo, hi; f2unpack(acc[p], lo, hi);
        float2 o;
        o.x = fmaxf(lo + bb.x, 0.f);
        o.y = fmaxf(hi + bb.y, 0.f);
        *(float2*)(g_x1 + ((size_t)(b * 256 + y) * 256 + (x0 + p)) * 64 + c0) = o;
    }
}

// ---------------- conv2: 3x3 s2, 64->256, relu; ci-pair packed ----------------
__global__ void __launch_bounds__(256, 2) conv2_kernel(const float* __restrict__ b2) {
    __shared__ __align__(16) float sm[9 * 17 * 64];
    int x0 = blockIdx.x * 8, y0 = blockIdx.y * 4, b = blockIdx.z;
    int t = threadIdx.x;
    for (int e = t; e < 9 * 17 * 64; e += 256) {
        int ci = e & 63; int rc = e >> 6; int c = rc % 17; int r = rc / 17;
        int iy = 2 * y0 + r, ix = 2 * x0 + c;
        float v = 0.f;
        if (iy < 256 && ix < 256) v = g_x1[((size_t)(b * 256 + iy) * 256 + ix) * 64 + ci];
        sm[e] = v;
    }
    __syncthreads();
    int co4 = t & 63, ry = t >> 6;
    u64 acc[8][4];
#pragma unroll
    for (int p = 0; p < 8; p++)
#pragma unroll
        for (int j = 0; j < 4; j++) acc[p][j] = 0ull;
    const u64* wt2d = (const u64*)g_wt2;
#pragma unroll
    for (int ky = 0; ky < 3; ky++) {
        int r = 2 * ry + ky;
#pragma unroll
        for (int kx = 0; kx < 3; kx++) {
            const float* sbase = sm + (r * 17 + kx) * 64;
            const u64* wb = wt2d + (size_t)((ky * 3 + kx) * 32) * 256 + co4 * 4;
            for (int ci2 = 0; ci2 < 32; ci2++) {
                u64 v[8];
#pragma unroll
                for (int p = 0; p < 8; p++) v[p] = *(const u64*)(sbase + p * 128 + 2 * ci2);
                ulonglong2 wA = *(const ulonglong2*)(wb + (size_t)ci2 * 256);
                ulonglong2 wB = *(const ulonglong2*)(wb + (size_t)ci2 * 256 + 2);
#pragma unroll
                for (int p = 0; p < 8; p++) {
                    ffma2(acc[p][0], v[p], wA.x);
                    ffma2(acc[p][1], v[p], wA.y);
                    ffma2(acc[p][2], v[p], wB.x);
                    ffma2(acc[p][3], v[p], wB.y);
                }
            }
        }
    }
    int y = y0 + ry;
    float4 bb = *(const float4*)(b2 + co4 * 4);
#pragma unroll
    for (int p = 0; p < 8; p++) {
        float4 o;
        o.x = fmaxf(f2sum(acc[p][0]) + bb.x, 0.f);
        o.y = fmaxf(f2sum(acc[p][1]) + bb.y, 0.f);
        o.z = fmaxf(f2sum(acc[p][2]) + bb.z, 0.f);
        o.w = fmaxf(f2sum(acc[p][3]) + bb.w, 0.f);
        *(float4*)(g_feat + ((size_t)(b * 128 + y) * 128 + (x0 + p)) * 256 + co4 * 4) = o;
    }
}

// ---------------- detection heads: 4 px/warp, feature-column reuse ----------------
__global__ void heads_kernel(const float* __restrict__ bsc, const float* __restrict__ brg) {
    int b = blockIdx.y;
    int warp = threadIdx.x >> 5, lane = threadIdx.x & 31;
    int g = blockIdx.x * 8 + warp;         // 4096 groups of 4 pixels per batch
    int y = g >> 5, x0 = (g & 31) * 4;
    u64 aS[4], aY[4], aX[4];
#pragma unroll
    for (int p = 0; p < 4; p++) { aS[p] = 0ull; aY[p] = 0ull; aX[p] = 0ull; }
#pragma unroll
    for (int ky = 0; ky < 3; ky++) {
        int iy = y + ky - 1; if ((unsigned)iy >= 128u) continue;
        const u64* fprow = (const u64*)g_feat + (size_t)(b * 128 + iy) * 128 * 128;
#pragma unroll
        for (int q = 0; q < 4; q++) {
            int ci2 = lane + q * 32;
            u64 wS[3], wY[3], wX[3];
#pragma unroll
            for (int d = 0; d < 3; d++) {
                int tap = ky * 3 + d;
                wS[d] = __ldg((const u64*)g_wt_hs + tap * 128 + ci2);
                wY[d] = __ldg((const u64*)g_wt_hy + tap * 128 + ci2);
                wX[d] = __ldg((const u64*)g_wt_hx + tap * 128 + ci2);
            }
#pragma unroll
            for (int ixo = 0; ixo < 6; ixo++) {
                int ix = x0 - 1 + ixo;
                if ((unsigned)ix >= 128u) continue;
                u64 f = fprow[(size_t)ix * 128 + ci2];
#pragma unroll
                for (int p = 0; p < 4; p++) {
                    int d = ixo - p;       // dx index 0..2 when valid
                    if (d >= 0 && d < 3) {
                        ffma2(aS[p], f, wS[d]);
                        ffma2(aY[p], f, wY[d]);
                        ffma2(aX[p], f, wX[d]);
                    }
                }
            }
        }
    }
    float bsc0 = __ldg(bsc), brg0 = __ldg(brg), brg1 = __ldg(brg + 1);
#pragma unroll
    for (int p = 0; p < 4; p++) {
        float as = f2sum(aS[p]), ay = f2sum(aY[p]), ax = f2sum(aX[p]);
#pragma unroll
        for (int o = 16; o > 0; o >>= 1) {
            as += __shfl_down_sync(~0u, as, o);
            ay += __shfl_down_sync(~0u, ay, o);
            ax += __shfl_down_sync(~0u, ax, o);
        }
        if (lane == 0) {
            int px = y * 128 + x0 + p;
            g_scores[b * 16384 + px] = sigmoidf(as + bsc0);
            g_reg[(b * 16384 + px) * 2]     = ay + brg0;
            g_reg[(b * 16384 + px) * 2 + 1] = ax + brg1;
        }
    }
}

// ---------------- fused seg (1x1 256->256 relu) + segr (1x1 256->32 relu); ci-pair packed ----------------
__global__ void __launch_bounds__(256, 2) segseg_kernel(const float* __restrict__ bseg,
                                                        const float* __restrict__ br) {
    __shared__ __align__(16) float sf[32 * 256];
    int b = blockIdx.y; int p0 = blockIdx.x * 32; int t = threadIdx.x;
    {
        const float4* src = (const float4*)(g_feat + ((size_t)b * 16384 + p0) * 256);
        float4* dst4 = (float4*)sf;
        for (int e = t; e < 2048; e += 256) dst4[e] = src[e];
    }
    __syncthreads();
    int cg = t & 63, pg = t >> 6;
    int c0 = cg * 4;
    const float* sbase = sf + pg * 8 * 256;
    u64 acc[8][4];
#pragma unroll
    for (int p = 0; p < 8; p++)
#pragma unroll
        for (int j = 0; j < 4; j++) acc[p][j] = 0ull;
    const u64* wtd = (const u64*)g_wt_seg + c0;
    for (int ci2 = 0; ci2 < 128; ci2++) {
        u64 v[8];
#pragma unroll
        for (int p = 0; p < 8; p++) v[p] = *(const u64*)(sbase + p * 256 + 2 * ci2);
        ulonglong2 wA = *(const ulonglong2*)(wtd + (size_t)ci2 * 256);
        ulonglong2 wB = *(const ulonglong2*)(wtd + (size_t)ci2 * 256 + 2);
#pragma unroll
        for (int p = 0; p < 8; p++) {
            ffma2(acc[p][0], v[p], wA.x);
            ffma2(acc[p][1], v[p], wA.y);
            ffma2(acc[p][2], v[p], wB.x);
            ffma2(acc[p][3], v[p], wB.y);
        }
    }
    float bs[4];
#pragma unroll
    for (int j = 0; j < 4; j++) bs[j] = __ldg(bseg + c0 + j);
    __syncthreads();
#pragma unroll
    for (int p = 0; p < 8; p++) {
        float4 o;
        o.x = fmaxf(f2sum(acc[p][0]) + bs[0], 0.f);
        o.y = fmaxf(f2sum(acc[p][1]) + bs[1], 0.f);
        o.z = fmaxf(f2sum(acc[p][2]) + bs[2], 0.f);
        o.w = fmaxf(f2sum(acc[p][3]) + bs[3], 0.f);
        *(float4*)(sf + (pg * 8 + p) * 256 + c0) = o;
    }
    __syncthreads();
    int co = t & 31, pg2 = t >> 5;
    u64 a2[4];
#pragma unroll
    for (int q = 0; q < 4; q++) a2[q] = 0ull;
    const u64* wrd = (const u64*)g_wt_r + co;
    const float* s2 = sf + pg2 * 4 * 256;
    for (int ci2 = 0; ci2 < 128; ci2++) {
        u64 w = wrd[ci2 * 32];
#pragma unroll
        for (int q = 0; q < 4; q++)
            ffma2(a2[q], *(const u64*)(s2 + q * 256 + 2 * ci2), w);
    }
    float bc = __ldg(br + co);
#pragma unroll
    for (int q = 0; q < 4; q++)
        g_segr[((size_t)b * 16384 + p0 + pg2 * 4 + q) * 32 + co] = fmaxf(f2sum(a2[q]) + bc, 0.f);
}

// ---------------- top-K_PRE: blocked-register bitonic sort (16 keys/thread) ----------------
template<int J>
__device__ __forceinline__ void local_pass(u64 (&r)[16], int base, unsigned kk) {
#pragma unroll
    for (int i = 0; i < 16; i++)
        if ((i & J) == 0) {
            bool dsc = (((unsigned)(base + i) & kk) == 0);
            u64 A = r[i], C = r[i + J];
            if ((A < C) == dsc) { r[i] = C; r[i + J] = A; }
        }
}

__global__ void __launch_bounds__(1024) topk_kernel() {
    extern __shared__ unsigned long long sk[];   // padded: phys(e) = e + (e>>4)
    int b = blockIdx.x, t = threadIdx.x;
    int base = t * 16;
    u64 r[16];
#pragma unroll
    for (int i = 0; i < 16; i++) {
        int e = base + i;
        unsigned fb = __float_as_uint(g_scores[b * 16384 + e]);
        r[i] = ((u64)fb << 32) | (unsigned)(16383 - e);
    }
    // local rounds k=2..16 (all j<=8 intra-thread)
    local_pass<1>(r, base, 2);
    local_pass<2>(r, base, 4); local_pass<1>(r, base, 4);
    local_pass<4>(r, base, 8); local_pass<2>(r, base, 8); local_pass<1>(r, base, 8);
    local_pass<8>(r, base, 16); local_pass<4>(r, base, 16);
    local_pass<2>(r, base, 16); local_pass<1>(r, base, 16);
    for (unsigned k = 32; k <= 16384u; k <<= 1) {
#pragma unroll
        for (int i = 0; i < 16; i++) { int e = base + i; sk[e + (e >> 4)] = r[i]; }
        __syncthreads();
        for (unsigned j = k >> 1; j >= 16; j >>= 1) {
            for (unsigned e = t; e < 16384; e += 1024) {
                unsigned l = e ^ j;
                if (l > e) {
                    u64 A = sk[e + (e >> 4)], C = sk[l + (l >> 4)];
                    bool dsc = ((e & k) == 0);
                    if ((A < C) == dsc) { sk[e + (e >> 4)] = C; sk[l + (l >> 4)] = A; }
                }
            }
            __syncthreads();
        }
#pragma unroll
        for (int i = 0; i < 16; i++) { int e = base + i; r[i] = sk[e + (e >> 4)]; }
        local_pass<8>(r, base, k); local_pass<4>(r, base, k);
        local_pass<2>(r, base, k); local_pass<1>(r, base, k);
    }
#pragma unroll
    for (int i = 0; i < 16; i++) { int e = base + i; sk[e + (e >> 4)] = r[i]; }
    __syncthreads();
    for (int e = t; e < KPRE; e += 1024) {
        u64 key = sk[e + (e >> 4)];
        float s = __uint_as_float((unsigned)(key >> 32));
        int idx = 16383 - (int)(unsigned)(key & 0xFFFFFFFFu);
        g_topsc[b * KPRE + e] = s;
        float yy = (float)(idx >> 7), xx = (float)(idx & 127);
        g_locs[(b * KPRE + e) * 2]     = yy + 0.5f + g_reg[(b * 16384 + idx) * 2];
        g_locs[(b * KPRE + e) * 2 + 1] = xx + 0.5f + g_reg[(b * 16384 + idx) * 2 + 1];
    }
}

// ---------------- suppression bitmatrix: 32 i-rows per block, staged once ----------------
__global__ void sup_kernel() {
    __shared__ float sy[32 * 65];
    __shared__ float sx[32 * 65];
    int b = blockIdx.y, i0 = blockIdx.x * 32, t = threadIdx.x;   // 256 threads
    for (int j = t; j < KPRE; j += 256) {
        float2 lj = *(const float2*)(g_locs + (b * KPRE + j) * 2);
        sy[(j & 31) * 65 + (j >> 5)] = lj.x;
        sx[(j & 31) * 65 + (j >> 5)] = lj.y;
    }
    __syncthreads();
    int wq = t & 63;
#pragma unroll
    for (int k = 0; k < 8; k++) {
        int il = (t >> 6) + k * 4;               // 0..31
        int i = i0 + il;
        if (i >= KPRE) continue;
        float ly = sy[(i & 31) * 65 + (i >> 5)];
        float lx = sx[(i & 31) * 65 + (i >> 5)];
        unsigned bits = 0;
        if (wq < 63) {
#pragma unroll 4
            for (int u = 0; u < 32; u++) {
                int j = wq * 32 + u;
                if (j < KPRE) {
                    float dy = ly - sy[u * 65 + wq];
                    float dx = lx - sx[u * 65 + wq];
                    if (sqrtf(dy * dy + dx * dx) <= 1.1f) bits |= (1u << u);
                }
            }
        }
        g_sup[((size_t)(b * KPRE) + i) * 64 + wq] = bits;
    }
}

// ---------------- sequential greedy NMS scan; early exit once KOUT kept ----------------
__global__ void nms_scan_kernel() {
    int b = blockIdx.x, lane = threadIdx.x;   // 32 threads
    __shared__ unsigned ssup[64];
    __shared__ int slist[KOUT];
    ssup[lane] = 0; ssup[lane + 32] = 0;
    __syncwarp();
    const unsigned* base = g_sup + (size_t)b * KPRE * 64;
    unsigned ca[8], cb[8], na[8], nb[8];
#pragma unroll
    for (int u = 0; u < 8; u++) {
        ca[u] = base[(size_t)u * 64 + lane];
        cb[u] = (lane < 31) ? base[(size_t)u * 64 + 32 + lane] : 0u;
    }
    int cnt = 0;
    for (int ch = 0; ch < KPRE; ch += 8) {
        if (ch + 8 < KPRE) {
#pragma unroll
            for (int u = 0; u < 8; u++) {
                int i = ch + 8 + u;
                na[u] = base[(size_t)i * 64 + lane];
                nb[u] = (lane < 31) ? base[(size_t)i * 64 + 32 + lane] : 0u;
            }
        }
#pragma unroll
        for (int u = 0; u < 8; u++) {
            int i = ch + u;
            bool kp = ((ssup[i >> 5] >> (i & 31)) & 1u) == 0u;
            if (kp) {
                ssup[lane] |= ca[u];
                if (lane < 31) ssup[32 + lane] |= cb[u];
                if (lane == 0) { if (cnt < KOUT) slist[cnt] = i; cnt++; }
            }
            __syncwarp();
        }
        // early exit: once KOUT kept, later decisions cannot affect any output
        int c0 = __shfl_sync(~0u, cnt, 0);
        if (c0 >= KOUT) break;
#pragma unroll
        for (int u = 0; u < 8; u++) { ca[u] = na[u]; cb[u] = nb[u]; }
    }
    cnt = __shfl_sync(~0u, cnt, 0);
    if (lane == 0) g_nsel[b] = cnt;
    __syncwarp();
    int n = cnt < KOUT ? cnt : KOUT;
    for (int k = lane; k < n; k += 32) g_sel[b * KOUT + k] = slist[k];
}

// ---------------- selection: sel_s, pix outputs + crop top-lefts ----------------
__global__ void select_kernel(float* __restrict__ out) {
    int b = blockIdx.x; int k = threadIdx.x;
    if (k >= KOUT) return;
    int n = g_nsel[b]; if (n > KOUT) n = KOUT;
    bool valid = (k < n);
    float s = -1.f, ly = 0.f, lx = 0.f;
    if (valid) {
        int i = g_sel[b * KOUT + k];
        s  = g_topsc[b * KPRE + i];
        ly = g_locs[(b * KPRE + i) * 2];
        lx = g_locs[(b * KPRE + i) * 2 + 1];
    }
    float cy, cx;
    int o = b * KOUT + k;
    if (valid) {
        out[o] = s;
        out[2000 + o * 2]     = ly * 4.f;
        out[2000 + o * 2 + 1] = lx * 4.f;
        cy = ly; cx = lx;
    } else {
        out[o] = -1.f;
        out[2000 + o * 2] = -1.f;
        out[2000 + o * 2 + 1] = -1.f;
        cy = -0.25f; cx = -0.25f;    // pix=-1 -> (-1/512)*128
    }
    int ty = (int)rintf(cy) - 16; ty = min(max(ty, 0), 96);
    int tx = (int)rintf(cx) - 16; tx = min(max(tx, 0), 96);
    g_tl[o * 2] = ty; g_tl[o * 2 + 1] = tx;
}

// ---------------- inst_full: 4 px/warp; lane-consecutive weights + broadcast .128 acts ----------------
__global__ void instfull_kernel(const float* __restrict__ bp1v,
                                const float* __restrict__ wp2, const float* __restrict__ bp2v) {
    int t = threadIdx.x;
    int b = blockIdx.y;
    int wi = t >> 5, lane = t & 31;
    int g = blockIdx.x * 8 + wi;           // 4096 groups of 4 pixels
    int y = g >> 5, x0 = (g & 31) * 4;
    const u64* wsd = (const u64*)g_wt_p1;  // [tap][ci2][co]
    u64 acc[4];
#pragma unroll
    for (int p = 0; p < 4; p++) acc[p] = 0ull;
#pragma unroll
    for (int dy = -1; dy <= 1; dy++) {
        int iy = y + dy; if ((unsigned)iy >= 128u) continue;
#pragma unroll
        for (int dx = -1; dx <= 1; dx++) {
            int tap = (dy + 1) * 3 + (dx + 1);
            const u64* wb = wsd + tap * 512 + lane;
            u64 w[16];
#pragma unroll
            for (int i = 0; i < 16; i++) w[i] = __ldg(wb + i * 32);
#pragma unroll
            for (int p = 0; p < 4; p++) {
                int ix = x0 + p + dx; if ((unsigned)ix >= 128u) continue;
                const ulonglong2* sp = (const ulonglong2*)(g_segr + ((size_t)(b * 128 + iy) * 128 + ix) * 32);
#pragma unroll
                for (int i = 0; i < 8; i++) {
                    ulonglong2 s = __ldg(sp + i);
                    ffma2(acc[p], s.x, w[2 * i]);
                    ffma2(acc[p], s.y, w[2 * i + 1]);
                }
            }
        }
    }
    float b1l = __ldg(bp1v + lane), w2l = __ldg(wp2 + lane);
    float bp2s = __ldg(bp2v);
#pragma unroll
    for (int p = 0; p < 4; p++) {
        int x = x0 + p;
        float a = f2sum(acc[p]);
        g_acc1[((size_t)(b * 128 + y) * 128 + x) * 32 + lane] = a;
        float h = fmaxf(a + b1l, 0.f);
        float v = h * w2l;
#pragma unroll
        for (int o = 16; o > 0; o >>= 1) v += __shfl_down_sync(~0u, v, o);
        if (lane == 0) g_instfull[(size_t)(b * 128 + y) * 128 + x] = sigmoidf(v + bp2s);
    }
}

// ---------------- per-patch: gather interior; border via acc1 subtraction ----------------
__global__ void patch_kernel(const float* __restrict__ bp1v,
                             const float* __restrict__ wp2, const float* __restrict__ bp2v,
                             float* __restrict__ out) {
    int blk = blockIdx.x; int b = blk / KOUT, k = blk % KOUT;
    int t = threadIdx.x;
    int ty = g_tl[(b * KOUT + k) * 2], tx = g_tl[(b * KOUT + k) * 2 + 1];
    float* obase = out + 6000 + ((size_t)(b * KOUT + k)) * 1024;
    for (int e = t; e < 1024; e += 256) {
        int py = e >> 5, px = e & 31;
        if (py >= 1 && py <= 30 && px >= 1 && px <= 30)
            obase[e] = g_instfull[(size_t)(b * 128 + ty + py) * 128 + tx + px];
    }
    float bp2s = __ldg(bp2v);
    int warp = t >> 5, lane = t & 31;
    const u64* wsd = (const u64*)g_wt_p1;
    float sb1l = __ldg(bp1v + lane);
    float sw2l = __ldg(wp2 + lane);
    for (int bp = warp; bp < 124; bp += 8) {
        int py, px;
        if (bp < 32)      { py = 0;       px = bp; }
        else if (bp < 64) { py = 31;      px = bp - 32; }
        else if (bp < 94) { py = bp - 63; px = 0; }
        else              { py = bp - 93; px = 31; }
        int gy = ty + py, gx = tx + px;
        u64 corr = 0ull;
#pragma unroll
        for (int dy = -1; dy <= 1; dy++) {
            int ly = py + dy, yy = gy + dy;
#pragma unroll
            for (int dx = -1; dx <= 1; dx++) {
                int lx = px + dx, xx = gx + dx;
                bool outside_patch = ((unsigned)ly >= 32u) || ((unsigned)lx >= 32u);
                bool inside_global = ((unsigned)yy < 128u) && ((unsigned)xx < 128u);
                if (outside_patch && inside_global) {
                    int tap = (dy + 1) * 3 + (dx + 1);
                    const u64* wb = wsd + tap * 512 + lane;
                    const ulonglong2* sp = (const ulonglong2*)(g_segr + ((size_t)(b * 128 + yy) * 128 + xx) * 32);
#pragma unroll
                    for (int i = 0; i < 8; i++) {
                        ulonglong2 s = __ldg(sp + i);
                        ffma2(corr, s.x, __ldg(wb + (2 * i) * 32));
                        ffma2(corr, s.y, __ldg(wb + (2 * i + 1) * 32));
                    }
                }
            }
        }
        float a = g_acc1[((size_t)(b * 128 + gy) * 128 + gx) * 32 + lane] - f2sum(corr);
        float h = fmaxf(a + sb1l, 0.f);
        float v = h * sw2l;
#pragma unroll
        for (int o = 16; o > 0; o >>= 1) v += __shfl_down_sync(~0u, v, o);
        if (lane == 0) obase[py * 32 + px] = sigmoidf(v + bp2s);
    }
}

// ---------------- launch ----------------
extern "C" void kernel_launch(void* const* d_in, const int* in_sizes, int n_in,
                              void* d_out, int out_size) {
    const float* image = (const float*)d_in[0];
    const float* w1   = (const float*)d_in[1];
    const float* b1   = (const float*)d_in[2];
    const float* w2   = (const float*)d_in[3];
    const float* b2   = (const float*)d_in[4];
    const float* wseg = (const float*)d_in[5];
    const float* bseg = (const float*)d_in[6];
    const float* wsc  = (const float*)d_in[7];
    const float* bsc  = (const float*)d_in[8];
    const float* wrg  = (const float*)d_in[9];
    const float* brg  = (const float*)d_in[10];
    const float* wr   = (const float*)d_in[11];
    const float* br   = (const float*)d_in[12];
    const float* wp1  = (const float*)d_in[13];
    const float* bp1  = (const float*)d_in[14];
    const float* wp2  = (const float*)d_in[15];
    const float* bp2  = (const float*)d_in[16];
    float* out = (float*)d_out;

    cudaFuncSetAttribute(topk_kernel, cudaFuncAttributeMaxDynamicSharedMemorySize, 139264);

    tr_all_kernel<<<927, 256>>>(wseg, wr, w2, wsc, wrg, wp1);

    conv1_kernel<<<dim3(32, 32, 4), 256>>>(image, w1, b1);
    conv2_kernel<<<dim3(16, 32, 4), 256>>>(b2);
    heads_kernel<<<dim3(512, 4), 256>>>(bsc, brg);
    segseg_kernel<<<dim3(512, 4), 256>>>(bseg, br);
    topk_kernel<<<4, 1024, 139264>>>();
    sup_kernel<<<dim3(63, 4), 256>>>();
    nms_scan_kernel<<<4, 32>>>();
    select_kernel<<<4, 512>>>(out);
    instfull_kernel<<<dim3(512, 4), 256>>>(bp1, wp2, bp2);
    patch_kernel<<<BB * KOUT, 256>>>(bp1, wp2, bp2, out);
}